// round 6
// baseline (speedup 1.0000x reference)
#include <cuda_runtime.h>
#include <math.h>
#include <stdint.h>

#define BB 4
#define CC 64
#define HW 4096
#define CHW (CC*HW)
#define EPSV 1e-5f
#define OFRV 4.0f
#define SCALEV 0.125f

// -------- scratch (device globals) --------
__device__ float g_q [BB*CHW];   // [b][p][c]
__device__ float g_k [BB*CHW];   // [b][n][c]
__device__ float g_v [BB*CHW];   // [b][n][c]
__device__ float g_ao[BB*CHW];   // [b][p][c]
__device__ float g_vsum[BB*CC];  // colsum of V per (batch, channel)

// ================= helpers =================
__device__ __forceinline__ uint32_t smem_u32(const void* p){
    uint32_t a;
    asm("{ .reg .u64 t; cvta.to.shared.u64 t, %1; cvt.u32.u64 %0, t; }" : "=r"(a) : "l"(p));
    return a;
}
__device__ __forceinline__ void cp16(uint32_t dst, const void* src){
    asm volatile("cp.async.cg.shared.global [%0], [%1], 16;" :: "r"(dst), "l"(src));
}
#define CP_COMMIT() asm volatile("cp.async.commit_group;" ::: "memory")
#define CP_WAIT0()  asm volatile("cp.async.wait_group 0;" ::: "memory")
#define CP_WAIT1()  asm volatile("cp.async.wait_group 1;" ::: "memory")

__device__ __forceinline__ void mma_tf32(float* d, const uint32_t* a,
                                         uint32_t b0, uint32_t b1, const float* c){
    asm volatile(
        "mma.sync.aligned.m16n8k8.row.col.f32.tf32.tf32.f32 "
        "{%0,%1,%2,%3}, {%4,%5,%6,%7}, {%8,%9}, {%10,%11,%12,%13};"
        : "=f"(d[0]), "=f"(d[1]), "=f"(d[2]), "=f"(d[3])
        : "r"(a[0]), "r"(a[1]), "r"(a[2]), "r"(a[3]),
          "r"(b0), "r"(b1),
          "f"(c[0]), "f"(c[1]), "f"(c[2]), "f"(c[3]));
}

// ================= conv1x1 q: prompt [c][p] -> g_q [p][c]
// 256 thr, 64 pixels/block, each thread: quarter of output channels (16)
__global__ void k_convq(const float* __restrict__ prompt,
                        const float* __restrict__ wq,
                        const float* __restrict__ bq) {
    __shared__ float ws[4096];
    __shared__ float bs[64];
    int tid = threadIdx.x;
    for (int i = tid; i < 4096; i += 256) ws[i] = wq[i];
    if (tid < 64) bs[tid] = bq[tid];
    __syncthreads();
    int qtr = tid >> 6;                 // 0..3
    int p   = blockIdx.x * 64 + (tid & 63);
    int bb  = blockIdx.y;
    const float* xb = prompt + bb * CHW + p;
    float xr[64];
#pragma unroll
    for (int c = 0; c < 64; c++) xr[c] = xb[c * HW];
    float4* yb = (float4*)(g_q + bb * CHW + p * 64 + qtr * 16);
    const float* wbase = ws + qtr * 16 * 64;
#pragma unroll
    for (int o4 = 0; o4 < 4; o4++) {
        float a0 = bs[qtr*16 + o4*4 + 0], a1 = bs[qtr*16 + o4*4 + 1];
        float a2 = bs[qtr*16 + o4*4 + 2], a3 = bs[qtr*16 + o4*4 + 3];
#pragma unroll
        for (int c = 0; c < 64; c++) {
            float x = xr[c];
            a0 += wbase[(o4*4+0)*64 + c] * x;
            a1 += wbase[(o4*4+1)*64 + c] * x;
            a2 += wbase[(o4*4+2)*64 + c] * x;
            a3 += wbase[(o4*4+3)*64 + c] * x;
        }
        yb[o4] = make_float4(a0, a1, a2, a3);
    }
}

// ================= conv1x1 out: g_ao [p][c] -> out [c][p]
__global__ void k_convo(const float* __restrict__ wo,
                        const float* __restrict__ bo,
                        float* __restrict__ out) {
    __shared__ float ws[4096];
    __shared__ float bs[64];
    int tid = threadIdx.x;
    for (int i = tid; i < 4096; i += 256) ws[i] = wo[i];
    if (tid < 64) bs[tid] = bo[tid];
    __syncthreads();
    int qtr = tid >> 6;
    int p   = blockIdx.x * 64 + (tid & 63);
    int bb  = blockIdx.y;
    const float4* xb4 = (const float4*)(g_ao + bb * CHW + p * 64);
    float xr[64];
#pragma unroll
    for (int c4 = 0; c4 < 16; c4++) {
        float4 v = xb4[c4];
        xr[c4*4+0] = v.x; xr[c4*4+1] = v.y; xr[c4*4+2] = v.z; xr[c4*4+3] = v.w;
    }
    float* yb = out + bb * CHW + (qtr * 16) * HW + p;
    const float* wbase = ws + qtr * 16 * 64;
#pragma unroll
    for (int o4 = 0; o4 < 4; o4++) {
        float a0 = bs[qtr*16 + o4*4 + 0], a1 = bs[qtr*16 + o4*4 + 1];
        float a2 = bs[qtr*16 + o4*4 + 2], a3 = bs[qtr*16 + o4*4 + 3];
#pragma unroll
        for (int c = 0; c < 64; c++) {
            float x = xr[c];
            a0 += wbase[(o4*4+0)*64 + c] * x;
            a1 += wbase[(o4*4+1)*64 + c] * x;
            a2 += wbase[(o4*4+2)*64 + c] * x;
            a3 += wbase[(o4*4+3)*64 + c] * x;
        }
        yb[(o4*4+0) * HW] = a0;
        yb[(o4*4+1) * HW] = a1;
        yb[(o4*4+2) * HW] = a2;
        yb[(o4*4+3) * HW] = a3;
    }
}

// ================= fused: dw3x3 + LN + GELU + offset + tanh + bilinear + K/V proj
__global__ void k_fuse(const float* __restrict__ kv,
                       const float* __restrict__ dw_w,
                       const float* __restrict__ dw_b,
                       const float* __restrict__ ln_w,
                       const float* __restrict__ ln_b,
                       const float* __restrict__ off_w,
                       const float* __restrict__ wk,
                       const float* __restrict__ bk,
                       const float* __restrict__ wv,
                       const float* __restrict__ bv) {
    __shared__ float s_wk[4096], s_wv[4096];
    __shared__ float s_dw[576], s_dwb[64], s_lnw[64], s_lnb[64];
    __shared__ float s_offw[128], s_bk[64], s_bv[64];

    for (int i = threadIdx.x; i < 4096; i += 128) { s_wk[i] = wk[i]; s_wv[i] = wv[i]; }
    for (int i = threadIdx.x; i < 576; i += 128) s_dw[i] = dw_w[i];
    if (threadIdx.x < 64) {
        s_dwb[threadIdx.x] = dw_b[threadIdx.x];
        s_lnw[threadIdx.x] = ln_w[threadIdx.x];
        s_lnb[threadIdx.x] = ln_b[threadIdx.x];
        s_bk[threadIdx.x]  = bk[threadIdx.x];
        s_bv[threadIdx.x]  = bv[threadIdx.x];
    }
    if (threadIdx.x < 128) s_offw[threadIdx.x] = off_w[threadIdx.x];
    __syncthreads();

    int p  = blockIdx.x * 128 + threadIdx.x;
    int bb = blockIdx.y;
    int py = p >> 6;
    int px = p & 63;

    const float* qb = g_q + bb * CHW;   // [p][c]

    float t[64];
#pragma unroll
    for (int c = 0; c < 64; c++) t[c] = s_dwb[c];

    for (int k9 = 0; k9 < 9; k9++) {
        int dy = k9 / 3 - 1, dx = k9 % 3 - 1;
        int yy = py + dy, xx = px + dx;
        if (yy < 0 || yy > 63 || xx < 0 || xx > 63) continue;
        const float4* qp = (const float4*)(qb + (yy * 64 + xx) * 64);
#pragma unroll
        for (int c4 = 0; c4 < 16; c4++) {
            float4 qv = qp[c4];
            t[c4*4+0] += qv.x * s_dw[(c4*4+0)*9 + k9];
            t[c4*4+1] += qv.y * s_dw[(c4*4+1)*9 + k9];
            t[c4*4+2] += qv.z * s_dw[(c4*4+2)*9 + k9];
            t[c4*4+3] += qv.w * s_dw[(c4*4+3)*9 + k9];
        }
    }

    float mu = 0.f;
#pragma unroll
    for (int c = 0; c < 64; c++) mu += t[c];
    mu *= (1.0f / 64.0f);
    float var = 0.f;
#pragma unroll
    for (int c = 0; c < 64; c++) { float d = t[c] - mu; var += d * d; }
    var *= (1.0f / 64.0f);
    float rstd = rsqrtf(var + EPSV);
#pragma unroll
    for (int c = 0; c < 64; c++) {
        float z = (t[c] - mu) * rstd * s_lnw[c] + s_lnb[c];
        t[c] = 0.5f * z * (1.0f + erff(z * 0.70710678118654752f));
    }

    float o0 = 0.f, o1 = 0.f;
#pragma unroll
    for (int c = 0; c < 64; c++) { o0 += s_offw[c] * t[c]; o1 += s_offw[64 + c] * t[c]; }
    float off0 = tanhf(o0) * (1.0f / 63.0f) * OFRV;
    float off1 = tanhf(o1) * (1.0f / 63.0f) * OFRV;

    float refy = (0.5f + (float)py) * (2.0f / 63.0f) - 1.0f;
    float refx = (0.5f + (float)px) * (2.0f / 63.0f) - 1.0f;
    float gx = (off1 + refx + 1.0f) * 0.5f * 63.0f;
    float gy = (off0 + refy + 1.0f) * 0.5f * 63.0f;

    float x0f = floorf(gx), y0f = floorf(gy);
    float wx = gx - x0f, wy = gy - y0f;
    int x0 = (int)x0f, y0 = (int)y0f;
    int x1 = x0 + 1,   y1 = y0 + 1;

    float m00 = (x0 >= 0 && x0 <= 63 && y0 >= 0 && y0 <= 63) ? 1.f : 0.f;
    float m01 = (x1 >= 0 && x1 <= 63 && y0 >= 0 && y0 <= 63) ? 1.f : 0.f;
    float m10 = (x0 >= 0 && x0 <= 63 && y1 >= 0 && y1 <= 63) ? 1.f : 0.f;
    float m11 = (x1 >= 0 && x1 <= 63 && y1 >= 0 && y1 <= 63) ? 1.f : 0.f;

    int xc0 = min(max(x0, 0), 63), xc1 = min(max(x1, 0), 63);
    int yc0 = min(max(y0, 0), 63), yc1 = min(max(y1, 0), 63);

    float w00 = m00 * (1.0f - wx) * (1.0f - wy);
    float w01 = m01 * wx * (1.0f - wy);
    float w10 = m10 * (1.0f - wx) * wy;
    float w11 = m11 * wx * wy;

    int i00 = yc0 * 64 + xc0, i01 = yc0 * 64 + xc1;
    int i10 = yc1 * 64 + xc0, i11 = yc1 * 64 + xc1;

    const float* kvb = kv + bb * CHW;
#pragma unroll
    for (int c = 0; c < 64; c++) {
        const float* kc = kvb + c * HW;
        t[c] = w00 * kc[i00] + w01 * kc[i01] + w10 * kc[i10] + w11 * kc[i11];
    }

    float* kout = g_k + bb * CHW + p * 64;   // [n][c]
    float* vout = g_v + bb * CHW + p * 64;   // [n][c]
    for (int o4 = 0; o4 < 16; o4++) {
        float ka[4], va[4];
#pragma unroll
        for (int i = 0; i < 4; i++) { ka[i] = s_bk[o4*4+i]; va[i] = s_bv[o4*4+i]; }
#pragma unroll
        for (int c = 0; c < 64; c++) {
            float x = t[c];
#pragma unroll
            for (int i = 0; i < 4; i++) {
                ka[i] += s_wk[(o4*4+i)*64 + c] * x;
                va[i] += s_wv[(o4*4+i)*64 + c] * x;
            }
        }
        ((float4*)kout)[o4] = make_float4(ka[0], ka[1], ka[2], ka[3]);
        ((float4*)vout)[o4] = make_float4(va[0], va[1], va[2], va[3]);
    }
}

// ================= V column sums (exact fp32, deterministic) =================
// grid = BB, block = 512: seg = tid>>6 (8 segments of 512 keys), c = tid&63
__global__ void k_vsum() {
    __shared__ float red[512];
    int tid = threadIdx.x;
    int bb  = blockIdx.x;
    int seg = tid >> 6;
    int c   = tid & 63;
    const float* vb = g_v + bb * CHW + c;
    float acc = 0.f;
    int n0 = seg * 512;
    for (int i = 0; i < 512; i += 4) {
        acc += vb[(n0 + i    ) * 64];
        acc += vb[(n0 + i + 1) * 64];
        acc += vb[(n0 + i + 2) * 64];
        acc += vb[(n0 + i + 3) * 64];
    }
    red[seg * 64 + c] = acc;
    __syncthreads();
    if (tid < 64) {
        float s = 0.f;
#pragma unroll
        for (int g = 0; g < 8; g++) s += red[g * 64 + tid];
        g_vsum[bb * 64 + tid] = s;
    }
}

// ================= mma.sync tf32 flash attention (P' = exp(s)-1 trick) =====
// 256 thr = 8 warps. M=128 queries/CTA. 128-key tiles, double-buffered.
#define KSTR 68
#define VSTR 72
#define PSTR 132
#define KS0 0
#define KS1 (128*KSTR)
#define VS0 (2*128*KSTR)
#define VS1 (2*128*KSTR + 128*VSTR)
#define PS  (2*128*KSTR + 2*128*VSTR)
#define ATTN_SMEM ((2*128*KSTR + 2*128*VSTR + 128*PSTR) * 4)

__global__ void __launch_bounds__(256) k_attn() {
    extern __shared__ float sm[];
    int tid  = threadIdx.x;
    int wid  = tid >> 5;
    int lane = tid & 31;
    int qr   = lane >> 2;   // 0..7
    int qc   = lane & 3;    // 0..3
    int bb = blockIdx.y;
    int m0 = blockIdx.x * 128;

    const float* qb = g_q + bb * CHW;
    const float* kb = g_k + bb * CHW;
    const float* vb = g_v + bb * CHW;

    uint32_t sbase = smem_u32(sm);

    // ---- Q fragments (persist in registers) ----
    uint32_t aq[8][4];
    {
        const float* qw = qb + (m0 + wid * 16) * 64;
#pragma unroll
        for (int kc = 0; kc < 8; kc++) {
            aq[kc][0] = __float_as_uint(qw[ qr      * 64 + kc*8 + qc    ]);
            aq[kc][1] = __float_as_uint(qw[(qr + 8) * 64 + kc*8 + qc    ]);
            aq[kc][2] = __float_as_uint(qw[ qr      * 64 + kc*8 + qc + 4]);
            aq[kc][3] = __float_as_uint(qw[(qr + 8) * 64 + kc*8 + qc + 4]);
        }
    }

    float oacc[8][4];
#pragma unroll
    for (int nc = 0; nc < 8; nc++)
#pragma unroll
        for (int j = 0; j < 4; j++) oacc[nc][j] = 0.f;
    float rs0 = 0.f, rs1 = 0.f;

    // ---- prefetch tile 0 (128 keys) ----
    {
#pragma unroll
        for (int it = 0; it < 8; it++) {
            int idx = tid + it * 256;          // 0..2047
            int key = idx >> 4, c4 = idx & 15;
            cp16(sbase + (KS0 + key * KSTR + c4 * 4) * 4, kb + key * 64 + c4 * 4);
            cp16(sbase + (VS0 + key * VSTR + c4 * 4) * 4, vb + key * 64 + c4 * 4);
        }
        CP_COMMIT();
    }

    float* Pw = sm + PS + (wid * 16) * PSTR;   // this warp's 16 P rows

    for (int i = 0; i < 32; i++) {
        __syncthreads();
        if (i + 1 < 32) {
            const float* ks = kb + (i + 1) * 128 * 64;
            const float* vs = vb + (i + 1) * 128 * 64;
            uint32_t ko = ((i + 1) & 1) ? KS1 : KS0;
            uint32_t vo = ((i + 1) & 1) ? VS1 : VS0;
#pragma unroll
            for (int it = 0; it < 8; it++) {
                int idx = tid + it * 256;
                int key = idx >> 4, c4 = idx & 15;
                cp16(sbase + (ko + key * KSTR + c4 * 4) * 4, ks + key * 64 + c4 * 4);
                cp16(sbase + (vo + key * VSTR + c4 * 4) * 4, vs + key * 64 + c4 * 4);
            }
            CP_COMMIT();
            CP_WAIT1();
        } else {
            CP_WAIT0();
        }
        __syncthreads();

        const float* Ks = sm + ((i & 1) ? KS1 : KS0);
        const float* Vs = sm + ((i & 1) ? VS1 : VS0);

        // ---- S = Q K^T; P' = exp(S*scale)-1 -> smem; rowsum += P' ----
#pragma unroll
        for (int nc = 0; nc < 16; nc++) {
            float s[4] = {0.f, 0.f, 0.f, 0.f};
            const float* kr0 = Ks + (nc * 8 + qr) * KSTR + qc;
#pragma unroll
            for (int kc = 0; kc < 8; kc++) {
                uint32_t b0 = __float_as_uint(kr0[kc * 8]);
                uint32_t b1 = __float_as_uint(kr0[kc * 8 + 4]);
                mma_tf32(s, aq[kc], b0, b1, s);
            }
            float e0 = __expf(s[0] * SCALEV) - 1.0f;
            float e1 = __expf(s[1] * SCALEV) - 1.0f;
            float e2 = __expf(s[2] * SCALEV) - 1.0f;
            float e3 = __expf(s[3] * SCALEV) - 1.0f;
            rs0 += e0 + e1;
            rs1 += e2 + e3;
            *(float2*)(Pw +  qr      * PSTR + nc * 8 + 2 * qc) = make_float2(e0, e1);
            *(float2*)(Pw + (qr + 8) * PSTR + nc * 8 + 2 * qc) = make_float2(e2, e3);
        }
        __syncwarp();

        // ---- O += P' @ V (k-dim = 128 keys, 16 chunks) ----
#pragma unroll
        for (int kc = 0; kc < 16; kc++) {
            uint32_t ap[4];
            ap[0] = __float_as_uint(Pw[ qr      * PSTR + kc*8 + qc    ]);
            ap[1] = __float_as_uint(Pw[(qr + 8) * PSTR + kc*8 + qc    ]);
            ap[2] = __float_as_uint(Pw[ qr      * PSTR + kc*8 + qc + 4]);
            ap[3] = __float_as_uint(Pw[(qr + 8) * PSTR + kc*8 + qc + 4]);
            const float* vr0 = Vs + (kc * 8 + qc) * VSTR + qr;
            const float* vr1 = Vs + (kc * 8 + qc + 4) * VSTR + qr;
#pragma unroll
            for (int nc = 0; nc < 8; nc++) {
                uint32_t b0 = __float_as_uint(vr0[nc * 8]);
                uint32_t b1 = __float_as_uint(vr1[nc * 8]);
                mma_tf32(oacc[nc], ap, b0, b1, oacc[nc]);
            }
        }
    }

    // ---- softmax normalization: rowsum = 4096 + sum(P') ----
    rs0 += __shfl_xor_sync(0xffffffffu, rs0, 1);
    rs0 += __shfl_xor_sync(0xffffffffu, rs0, 2);
    rs1 += __shfl_xor_sync(0xffffffffu, rs1, 1);
    rs1 += __shfl_xor_sync(0xffffffffu, rs1, 2);
    float inv0 = 1.0f / (4096.0f + rs0);
    float inv1 = 1.0f / (4096.0f + rs1);

    const float* vsum = g_vsum + bb * 64;
    float* ob = g_ao + bb * CHW + (m0 + wid * 16) * 64;
#pragma unroll
    for (int nc = 0; nc < 8; nc++) {
        float2 vs2 = *(const float2*)(vsum + nc * 8 + 2 * qc);
        *(float2*)(ob +  qr      * 64 + nc * 8 + 2 * qc) =
            make_float2((oacc[nc][0] + vs2.x) * inv0, (oacc[nc][1] + vs2.y) * inv0);
        *(float2*)(ob + (qr + 8) * 64 + nc * 8 + 2 * qc) =
            make_float2((oacc[nc][2] + vs2.x) * inv1, (oacc[nc][3] + vs2.y) * inv1);
    }
}

// ================= launch =================
extern "C" void kernel_launch(void* const* d_in, const int* in_sizes, int n_in,
                              void* d_out, int out_size) {
    const float* prompt = (const float*)d_in[0];
    const float* kv     = (const float*)d_in[1];
    const float* wq     = (const float*)d_in[2];
    const float* bq     = (const float*)d_in[3];
    const float* wk     = (const float*)d_in[4];
    const float* bk     = (const float*)d_in[5];
    const float* wv     = (const float*)d_in[6];
    const float* bv     = (const float*)d_in[7];
    const float* wo     = (const float*)d_in[8];
    const float* bo     = (const float*)d_in[9];
    const float* dw_w   = (const float*)d_in[10];
    const float* dw_b   = (const float*)d_in[11];
    const float* ln_w   = (const float*)d_in[12];
    const float* ln_b   = (const float*)d_in[13];
    const float* off_w  = (const float*)d_in[14];
    float* out = (float*)d_out;

    cudaFuncSetAttribute(k_attn, cudaFuncAttributeMaxDynamicSharedMemorySize, ATTN_SMEM);

    k_convq<<<dim3(64, BB), 256>>>(prompt, wq, bq);
    k_fuse <<<dim3(32, BB), 128>>>(kv, dw_w, dw_b, ln_w, ln_b, off_w, wk, bk, wv, bv);
    k_vsum <<<BB, 512>>>();
    k_attn <<<dim3(32, BB), 256, ATTN_SMEM>>>();
    k_convo<<<dim3(64, BB), 256>>>(wo, bo, out);
}

// round 7
// speedup vs baseline: 1.2016x; 1.2016x over previous
#include <cuda_runtime.h>
#include <math.h>
#include <stdint.h>

#define BB 4
#define CC 64
#define HW 4096
#define CHW (CC*HW)
#define EPSV 1e-5f
#define OFRV 4.0f
#define SCALEV 0.125f

// -------- scratch (device globals) --------
__device__ float g_q [BB*CHW];   // [b][p][c]
__device__ float g_k [BB*CHW];   // [b][n][c]
__device__ float g_v [BB*CHW];   // [b][n][c]
__device__ float g_ao[BB*CHW];   // [b][p][c]
__device__ float g_vsum[BB*CC];  // colsum of V per (batch, channel)

// ================= helpers =================
__device__ __forceinline__ uint32_t smem_u32(const void* p){
    uint32_t a;
    asm("{ .reg .u64 t; cvta.to.shared.u64 t, %1; cvt.u32.u64 %0, t; }" : "=r"(a) : "l"(p));
    return a;
}
__device__ __forceinline__ void cp16(uint32_t dst, const void* src){
    asm volatile("cp.async.cg.shared.global [%0], [%1], 16;" :: "r"(dst), "l"(src));
}
#define CP_COMMIT() asm volatile("cp.async.commit_group;" ::: "memory")
#define CP_WAIT0()  asm volatile("cp.async.wait_group 0;" ::: "memory")
#define CP_WAIT1()  asm volatile("cp.async.wait_group 1;" ::: "memory")

__device__ __forceinline__ void mma_tf32(float* d, const uint32_t* a,
                                         uint32_t b0, uint32_t b1, const float* c){
    asm volatile(
        "mma.sync.aligned.m16n8k8.row.col.f32.tf32.tf32.f32 "
        "{%0,%1,%2,%3}, {%4,%5,%6,%7}, {%8,%9}, {%10,%11,%12,%13};"
        : "=f"(d[0]), "=f"(d[1]), "=f"(d[2]), "=f"(d[3])
        : "r"(a[0]), "r"(a[1]), "r"(a[2]), "r"(a[3]),
          "r"(b0), "r"(b1),
          "f"(c[0]), "f"(c[1]), "f"(c[2]), "f"(c[3]));
}

// ================= conv1x1 q: prompt [c][p] -> g_q [p][c]
__global__ void k_convq(const float* __restrict__ prompt,
                        const float* __restrict__ wq,
                        const float* __restrict__ bq) {
    __shared__ float ws[4096];
    __shared__ float bs[64];
    int tid = threadIdx.x;
    for (int i = tid; i < 4096; i += 256) ws[i] = wq[i];
    if (tid < 64) bs[tid] = bq[tid];
    __syncthreads();
    int qtr = tid >> 6;                 // 0..3
    int p   = blockIdx.x * 64 + (tid & 63);
    int bb  = blockIdx.y;
    const float* xb = prompt + bb * CHW + p;
    float xr[64];
#pragma unroll
    for (int c = 0; c < 64; c++) xr[c] = xb[c * HW];
    float4* yb = (float4*)(g_q + bb * CHW + p * 64 + qtr * 16);
    const float* wbase = ws + qtr * 16 * 64;
#pragma unroll
    for (int o4 = 0; o4 < 4; o4++) {
        float a0 = bs[qtr*16 + o4*4 + 0], a1 = bs[qtr*16 + o4*4 + 1];
        float a2 = bs[qtr*16 + o4*4 + 2], a3 = bs[qtr*16 + o4*4 + 3];
#pragma unroll
        for (int c = 0; c < 64; c++) {
            float x = xr[c];
            a0 += wbase[(o4*4+0)*64 + c] * x;
            a1 += wbase[(o4*4+1)*64 + c] * x;
            a2 += wbase[(o4*4+2)*64 + c] * x;
            a3 += wbase[(o4*4+3)*64 + c] * x;
        }
        yb[o4] = make_float4(a0, a1, a2, a3);
    }
}

// ================= conv1x1 out: g_ao [p][c] -> out [c][p]
__global__ void k_convo(const float* __restrict__ wo,
                        const float* __restrict__ bo,
                        float* __restrict__ out) {
    __shared__ float ws[4096];
    __shared__ float bs[64];
    int tid = threadIdx.x;
    for (int i = tid; i < 4096; i += 256) ws[i] = wo[i];
    if (tid < 64) bs[tid] = bo[tid];
    __syncthreads();
    int qtr = tid >> 6;
    int p   = blockIdx.x * 64 + (tid & 63);
    int bb  = blockIdx.y;
    const float4* xb4 = (const float4*)(g_ao + bb * CHW + p * 64);
    float xr[64];
#pragma unroll
    for (int c4 = 0; c4 < 16; c4++) {
        float4 v = xb4[c4];
        xr[c4*4+0] = v.x; xr[c4*4+1] = v.y; xr[c4*4+2] = v.z; xr[c4*4+3] = v.w;
    }
    float* yb = out + bb * CHW + (qtr * 16) * HW + p;
    const float* wbase = ws + qtr * 16 * 64;
#pragma unroll
    for (int o4 = 0; o4 < 4; o4++) {
        float a0 = bs[qtr*16 + o4*4 + 0], a1 = bs[qtr*16 + o4*4 + 1];
        float a2 = bs[qtr*16 + o4*4 + 2], a3 = bs[qtr*16 + o4*4 + 3];
#pragma unroll
        for (int c = 0; c < 64; c++) {
            float x = xr[c];
            a0 += wbase[(o4*4+0)*64 + c] * x;
            a1 += wbase[(o4*4+1)*64 + c] * x;
            a2 += wbase[(o4*4+2)*64 + c] * x;
            a3 += wbase[(o4*4+3)*64 + c] * x;
        }
        yb[(o4*4+0) * HW] = a0;
        yb[(o4*4+1) * HW] = a1;
        yb[(o4*4+2) * HW] = a2;
        yb[(o4*4+3) * HW] = a3;
    }
}

// ================= fused: dw3x3 + LN + GELU + offset + tanh + bilinear + K/V proj
__global__ void k_fuse(const float* __restrict__ kv,
                       const float* __restrict__ dw_w,
                       const float* __restrict__ dw_b,
                       const float* __restrict__ ln_w,
                       const float* __restrict__ ln_b,
                       const float* __restrict__ off_w,
                       const float* __restrict__ wk,
                       const float* __restrict__ bk,
                       const float* __restrict__ wv,
                       const float* __restrict__ bv) {
    __shared__ float s_wk[4096], s_wv[4096];
    __shared__ float s_dw[576], s_dwb[64], s_lnw[64], s_lnb[64];
    __shared__ float s_offw[128], s_bk[64], s_bv[64];

    for (int i = threadIdx.x; i < 4096; i += 128) { s_wk[i] = wk[i]; s_wv[i] = wv[i]; }
    for (int i = threadIdx.x; i < 576; i += 128) s_dw[i] = dw_w[i];
    if (threadIdx.x < 64) {
        s_dwb[threadIdx.x] = dw_b[threadIdx.x];
        s_lnw[threadIdx.x] = ln_w[threadIdx.x];
        s_lnb[threadIdx.x] = ln_b[threadIdx.x];
        s_bk[threadIdx.x]  = bk[threadIdx.x];
        s_bv[threadIdx.x]  = bv[threadIdx.x];
    }
    if (threadIdx.x < 128) s_offw[threadIdx.x] = off_w[threadIdx.x];
    __syncthreads();

    int p  = blockIdx.x * 128 + threadIdx.x;
    int bb = blockIdx.y;
    int py = p >> 6;
    int px = p & 63;

    const float* qb = g_q + bb * CHW;   // [p][c]

    float t[64];
#pragma unroll
    for (int c = 0; c < 64; c++) t[c] = s_dwb[c];

    for (int k9 = 0; k9 < 9; k9++) {
        int dy = k9 / 3 - 1, dx = k9 % 3 - 1;
        int yy = py + dy, xx = px + dx;
        if (yy < 0 || yy > 63 || xx < 0 || xx > 63) continue;
        const float4* qp = (const float4*)(qb + (yy * 64 + xx) * 64);
#pragma unroll
        for (int c4 = 0; c4 < 16; c4++) {
            float4 qv = qp[c4];
            t[c4*4+0] += qv.x * s_dw[(c4*4+0)*9 + k9];
            t[c4*4+1] += qv.y * s_dw[(c4*4+1)*9 + k9];
            t[c4*4+2] += qv.z * s_dw[(c4*4+2)*9 + k9];
            t[c4*4+3] += qv.w * s_dw[(c4*4+3)*9 + k9];
        }
    }

    float mu = 0.f;
#pragma unroll
    for (int c = 0; c < 64; c++) mu += t[c];
    mu *= (1.0f / 64.0f);
    float var = 0.f;
#pragma unroll
    for (int c = 0; c < 64; c++) { float d = t[c] - mu; var += d * d; }
    var *= (1.0f / 64.0f);
    float rstd = rsqrtf(var + EPSV);
#pragma unroll
    for (int c = 0; c < 64; c++) {
        float z = (t[c] - mu) * rstd * s_lnw[c] + s_lnb[c];
        t[c] = 0.5f * z * (1.0f + erff(z * 0.70710678118654752f));
    }

    float o0 = 0.f, o1 = 0.f;
#pragma unroll
    for (int c = 0; c < 64; c++) { o0 += s_offw[c] * t[c]; o1 += s_offw[64 + c] * t[c]; }
    float off0 = tanhf(o0) * (1.0f / 63.0f) * OFRV;
    float off1 = tanhf(o1) * (1.0f / 63.0f) * OFRV;

    float refy = (0.5f + (float)py) * (2.0f / 63.0f) - 1.0f;
    float refx = (0.5f + (float)px) * (2.0f / 63.0f) - 1.0f;
    float gx = (off1 + refx + 1.0f) * 0.5f * 63.0f;
    float gy = (off0 + refy + 1.0f) * 0.5f * 63.0f;

    float x0f = floorf(gx), y0f = floorf(gy);
    float wx = gx - x0f, wy = gy - y0f;
    int x0 = (int)x0f, y0 = (int)y0f;
    int x1 = x0 + 1,   y1 = y0 + 1;

    float m00 = (x0 >= 0 && x0 <= 63 && y0 >= 0 && y0 <= 63) ? 1.f : 0.f;
    float m01 = (x1 >= 0 && x1 <= 63 && y0 >= 0 && y0 <= 63) ? 1.f : 0.f;
    float m10 = (x0 >= 0 && x0 <= 63 && y1 >= 0 && y1 <= 63) ? 1.f : 0.f;
    float m11 = (x1 >= 0 && x1 <= 63 && y1 >= 0 && y1 <= 63) ? 1.f : 0.f;

    int xc0 = min(max(x0, 0), 63), xc1 = min(max(x1, 0), 63);
    int yc0 = min(max(y0, 0), 63), yc1 = min(max(y1, 0), 63);

    float w00 = m00 * (1.0f - wx) * (1.0f - wy);
    float w01 = m01 * wx * (1.0f - wy);
    float w10 = m10 * (1.0f - wx) * wy;
    float w11 = m11 * wx * wy;

    int i00 = yc0 * 64 + xc0, i01 = yc0 * 64 + xc1;
    int i10 = yc1 * 64 + xc0, i11 = yc1 * 64 + xc1;

    const float* kvb = kv + bb * CHW;
#pragma unroll
    for (int c = 0; c < 64; c++) {
        const float* kc = kvb + c * HW;
        t[c] = w00 * kc[i00] + w01 * kc[i01] + w10 * kc[i10] + w11 * kc[i11];
    }

    float* kout = g_k + bb * CHW + p * 64;   // [n][c]
    float* vout = g_v + bb * CHW + p * 64;   // [n][c]
    for (int o4 = 0; o4 < 16; o4++) {
        float ka[4], va[4];
#pragma unroll
        for (int i = 0; i < 4; i++) { ka[i] = s_bk[o4*4+i]; va[i] = s_bv[o4*4+i]; }
#pragma unroll
        for (int c = 0; c < 64; c++) {
            float x = t[c];
#pragma unroll
            for (int i = 0; i < 4; i++) {
                ka[i] += s_wk[(o4*4+i)*64 + c] * x;
                va[i] += s_wv[(o4*4+i)*64 + c] * x;
            }
        }
        ((float4*)kout)[o4] = make_float4(ka[0], ka[1], ka[2], ka[3]);
        ((float4*)vout)[o4] = make_float4(va[0], va[1], va[2], va[3]);
    }
}

// ================= V column sums (exact fp32, deterministic) =================
__global__ void k_vsum() {
    __shared__ float red[512];
    int tid = threadIdx.x;
    int bb  = blockIdx.x;
    int seg = tid >> 6;
    int c   = tid & 63;
    const float* vb = g_v + bb * CHW + c;
    float acc = 0.f;
    int n0 = seg * 512;
    for (int i = 0; i < 512; i += 4) {
        acc += vb[(n0 + i    ) * 64];
        acc += vb[(n0 + i + 1) * 64];
        acc += vb[(n0 + i + 2) * 64];
        acc += vb[(n0 + i + 3) * 64];
    }
    red[seg * 64 + c] = acc;
    __syncthreads();
    if (tid < 64) {
        float s = 0.f;
#pragma unroll
        for (int g = 0; g < 8; g++) s += red[g * 64 + tid];
        g_vsum[bb * 64 + tid] = s;
    }
}

// ================= mma.sync tf32 flash attention =================
// 512 thr = 16 warps. 128 queries/CTA. Key-split: warp w -> query block (w&7),
// key half (w>>3) of each 128-key double-buffered tile. P' = exp(s)-1 trick.
#define KSTR 68
#define VSTR 72
#define PSTR 132
#define KS0 0
#define KS1 (128*KSTR)
#define VS0 (2*128*KSTR)
#define VS1 (2*128*KSTR + 128*VSTR)
#define PS  (2*128*KSTR + 2*128*VSTR)
#define ATTN_SMEM ((2*128*KSTR + 2*128*VSTR + 128*PSTR) * 4)

__global__ void __launch_bounds__(512) k_attn() {
    extern __shared__ float sm[];
    int tid  = threadIdx.x;
    int wid  = tid >> 5;
    int lane = tid & 31;
    int qw   = wid & 7;     // query 16-block
    int kh   = wid >> 3;    // key half (0/1)
    int qr   = lane >> 2;   // 0..7
    int qc   = lane & 3;    // 0..3
    int bb = blockIdx.y;
    int m0 = blockIdx.x * 128;

    const float* qb = g_q + bb * CHW;
    const float* kb = g_k + bb * CHW;
    const float* vb = g_v + bb * CHW;

    uint32_t sbase = smem_u32(sm);

    // ---- Q fragments (persist in registers) ----
    uint32_t aq[8][4];
    {
        const float* qw_ = qb + (m0 + qw * 16) * 64;
#pragma unroll
        for (int kc = 0; kc < 8; kc++) {
            aq[kc][0] = __float_as_uint(qw_[ qr      * 64 + kc*8 + qc    ]);
            aq[kc][1] = __float_as_uint(qw_[(qr + 8) * 64 + kc*8 + qc    ]);
            aq[kc][2] = __float_as_uint(qw_[ qr      * 64 + kc*8 + qc + 4]);
            aq[kc][3] = __float_as_uint(qw_[(qr + 8) * 64 + kc*8 + qc + 4]);
        }
    }

    float oacc[8][4];
#pragma unroll
    for (int nc = 0; nc < 8; nc++)
#pragma unroll
        for (int j = 0; j < 4; j++) oacc[nc][j] = 0.f;
    float rs0 = 0.f, rs1 = 0.f;

    // ---- prefetch tile 0 (128 keys), 512 threads ----
    {
#pragma unroll
        for (int it = 0; it < 4; it++) {
            int idx = tid + it * 512;          // 0..2047
            int key = idx >> 4, c4 = idx & 15;
            cp16(sbase + (KS0 + key * KSTR + c4 * 4) * 4, kb + key * 64 + c4 * 4);
            cp16(sbase + (VS0 + key * VSTR + c4 * 4) * 4, vb + key * 64 + c4 * 4);
        }
        CP_COMMIT();
    }

    // this warp's P quadrant: rows qw*16.., cols kh*64..
    float* Pw = sm + PS + (qw * 16) * PSTR + kh * 64;

    for (int i = 0; i < 32; i++) {
        __syncthreads();
        if (i + 1 < 32) {
            const float* ks = kb + (i + 1) * 128 * 64;
            const float* vs = vb + (i + 1) * 128 * 64;
            uint32_t ko = ((i + 1) & 1) ? KS1 : KS0;
            uint32_t vo = ((i + 1) & 1) ? VS1 : VS0;
#pragma unroll
            for (int it = 0; it < 4; it++) {
                int idx = tid + it * 512;
                int key = idx >> 4, c4 = idx & 15;
                cp16(sbase + (ko + key * KSTR + c4 * 4) * 4, ks + key * 64 + c4 * 4);
                cp16(sbase + (vo + key * VSTR + c4 * 4) * 4, vs + key * 64 + c4 * 4);
            }
            CP_COMMIT();
            CP_WAIT1();
        } else {
            CP_WAIT0();
        }
        __syncthreads();

        const float* Ks = sm + ((i & 1) ? KS1 : KS0) + kh * 64 * KSTR;
        const float* Vs = sm + ((i & 1) ? VS1 : VS0) + kh * 64 * VSTR;

        // ---- S = Q K^T over this key half; P' = exp(S*scale)-1 -> smem ----
#pragma unroll
        for (int nc = 0; nc < 8; nc++) {
            float s[4] = {0.f, 0.f, 0.f, 0.f};
            const float* kr0 = Ks + (nc * 8 + qr) * KSTR + qc;
#pragma unroll
            for (int kc = 0; kc < 8; kc++) {
                uint32_t b0 = __float_as_uint(kr0[kc * 8]);
                uint32_t b1 = __float_as_uint(kr0[kc * 8 + 4]);
                mma_tf32(s, aq[kc], b0, b1, s);
            }
            float e0 = __expf(s[0] * SCALEV) - 1.0f;
            float e1 = __expf(s[1] * SCALEV) - 1.0f;
            float e2 = __expf(s[2] * SCALEV) - 1.0f;
            float e3 = __expf(s[3] * SCALEV) - 1.0f;
            rs0 += e0 + e1;
            rs1 += e2 + e3;
            *(float2*)(Pw +  qr      * PSTR + nc * 8 + 2 * qc) = make_float2(e0, e1);
            *(float2*)(Pw + (qr + 8) * PSTR + nc * 8 + 2 * qc) = make_float2(e2, e3);
        }
        __syncwarp();

        // ---- O_partial += P'(half) @ V(half rows, all 64 cols) ----
#pragma unroll
        for (int kc = 0; kc < 8; kc++) {
            uint32_t ap[4];
            ap[0] = __float_as_uint(Pw[ qr      * PSTR + kc*8 + qc    ]);
            ap[1] = __float_as_uint(Pw[(qr + 8) * PSTR + kc*8 + qc    ]);
            ap[2] = __float_as_uint(Pw[ qr      * PSTR + kc*8 + qc + 4]);
            ap[3] = __float_as_uint(Pw[(qr + 8) * PSTR + kc*8 + qc + 4]);
            const float* vr0 = Vs + (kc * 8 + qc) * VSTR + qr;
            const float* vr1 = Vs + (kc * 8 + qc + 4) * VSTR + qr;
#pragma unroll
            for (int nc = 0; nc < 8; nc++) {
                uint32_t b0 = __float_as_uint(vr0[nc * 8]);
                uint32_t b1 = __float_as_uint(vr1[nc * 8]);
                mma_tf32(oacc[nc], ap, b0, b1, oacc[nc]);
            }
        }
    }

    // ---- combine key halves (reuse P region as scratch) ----
    __syncthreads();
    float* scr = sm + PS + qw * 1088;   // 1024 oacc + 64 rowsums per query block
    if (kh == 1) {
#pragma unroll
        for (int nc = 0; nc < 8; nc++) {
            *(float4*)(scr + lane * 32 + nc * 4) =
                make_float4(oacc[nc][0], oacc[nc][1], oacc[nc][2], oacc[nc][3]);
        }
        scr[1024 + lane]      = rs0;
        scr[1024 + 32 + lane] = rs1;
    }
    __syncthreads();
    if (kh == 0) {
#pragma unroll
        for (int nc = 0; nc < 8; nc++) {
            float4 o2 = *(const float4*)(scr + lane * 32 + nc * 4);
            oacc[nc][0] += o2.x; oacc[nc][1] += o2.y;
            oacc[nc][2] += o2.z; oacc[nc][3] += o2.w;
        }
        rs0 += scr[1024 + lane];
        rs1 += scr[1024 + 32 + lane];

        rs0 += __shfl_xor_sync(0xffffffffu, rs0, 1);
        rs0 += __shfl_xor_sync(0xffffffffu, rs0, 2);
        rs1 += __shfl_xor_sync(0xffffffffu, rs1, 1);
        rs1 += __shfl_xor_sync(0xffffffffu, rs1, 2);
        float inv0 = 1.0f / (4096.0f + rs0);
        float inv1 = 1.0f / (4096.0f + rs1);

        const float* vsum = g_vsum + bb * 64;
        float* ob = g_ao + bb * CHW + (m0 + qw * 16) * 64;
#pragma unroll
        for (int nc = 0; nc < 8; nc++) {
            float2 vs2 = *(const float2*)(vsum + nc * 8 + 2 * qc);
            *(float2*)(ob +  qr      * 64 + nc * 8 + 2 * qc) =
                make_float2((oacc[nc][0] + vs2.x) * inv0, (oacc[nc][1] + vs2.y) * inv0);
            *(float2*)(ob + (qr + 8) * 64 + nc * 8 + 2 * qc) =
                make_float2((oacc[nc][2] + vs2.x) * inv1, (oacc[nc][3] + vs2.y) * inv1);
        }
    }
}

// ================= launch =================
extern "C" void kernel_launch(void* const* d_in, const int* in_sizes, int n_in,
                              void* d_out, int out_size) {
    const float* prompt = (const float*)d_in[0];
    const float* kv     = (const float*)d_in[1];
    const float* wq     = (const float*)d_in[2];
    const float* bq     = (const float*)d_in[3];
    const float* wk     = (const float*)d_in[4];
    const float* bk     = (const float*)d_in[5];
    const float* wv     = (const float*)d_in[6];
    const float* bv     = (const float*)d_in[7];
    const float* wo     = (const float*)d_in[8];
    const float* bo     = (const float*)d_in[9];
    const float* dw_w   = (const float*)d_in[10];
    const float* dw_b   = (const float*)d_in[11];
    const float* ln_w   = (const float*)d_in[12];
    const float* ln_b   = (const float*)d_in[13];
    const float* off_w  = (const float*)d_in[14];
    float* out = (float*)d_out;

    cudaFuncSetAttribute(k_attn, cudaFuncAttributeMaxDynamicSharedMemorySize, ATTN_SMEM);

    k_convq<<<dim3(64, BB), 256>>>(prompt, wq, bq);
    k_fuse <<<dim3(32, BB), 128>>>(kv, dw_w, dw_b, ln_w, ln_b, off_w, wk, bk, wv, bv);
    k_vsum <<<BB, 512>>>();
    k_attn <<<dim3(32, BB), 512, ATTN_SMEM>>>();
    k_convo<<<dim3(64, BB), 256>>>(wo, bo, out);
}

// round 8
// speedup vs baseline: 1.2521x; 1.0421x over previous
#include <cuda_runtime.h>
#include <math.h>
#include <stdint.h>

#define BB 4
#define CC 64
#define HW 4096
#define CHW (CC*HW)
#define EPSV 1e-5f
#define OFRV 4.0f
#define SCALEV 0.125f

// -------- scratch (device globals) --------
__device__ float g_q [BB*CHW];   // [b][p][c]
__device__ float g_k [BB*CHW];   // [b][n][c]
__device__ float g_v [BB*CHW];   // [b][n][c]
__device__ float g_ao[BB*CHW];   // [b][p][c]
__device__ float g_vsum[BB*CC];  // colsum of V per (batch, channel)

// ================= helpers =================
__device__ __forceinline__ uint32_t smem_u32(const void* p){
    uint32_t a;
    asm("{ .reg .u64 t; cvta.to.shared.u64 t, %1; cvt.u32.u64 %0, t; }" : "=r"(a) : "l"(p));
    return a;
}
__device__ __forceinline__ void cp16(uint32_t dst, const void* src){
    asm volatile("cp.async.cg.shared.global [%0], [%1], 16;" :: "r"(dst), "l"(src));
}
#define CP_COMMIT() asm volatile("cp.async.commit_group;" ::: "memory")
#define CP_WAIT0()  asm volatile("cp.async.wait_group 0;" ::: "memory")
#define CP_WAIT1()  asm volatile("cp.async.wait_group 1;" ::: "memory")

__device__ __forceinline__ void mma_tf32(float* d, const uint32_t* a,
                                         uint32_t b0, uint32_t b1, const float* c){
    asm volatile(
        "mma.sync.aligned.m16n8k8.row.col.f32.tf32.tf32.f32 "
        "{%0,%1,%2,%3}, {%4,%5,%6,%7}, {%8,%9}, {%10,%11,%12,%13};"
        : "=f"(d[0]), "=f"(d[1]), "=f"(d[2]), "=f"(d[3])
        : "r"(a[0]), "r"(a[1]), "r"(a[2]), "r"(a[3]),
          "r"(b0), "r"(b1),
          "f"(c[0]), "f"(c[1]), "f"(c[2]), "f"(c[3]));
}

// ================= conv1x1 q: prompt [c][p] -> g_q [p][c]
__global__ void k_convq(const float* __restrict__ prompt,
                        const float* __restrict__ wq,
                        const float* __restrict__ bq) {
    __shared__ float ws[4096];
    __shared__ float bs[64];
    int tid = threadIdx.x;
    for (int i = tid; i < 4096; i += 256) ws[i] = wq[i];
    if (tid < 64) bs[tid] = bq[tid];
    __syncthreads();
    int qtr = tid >> 6;                 // 0..3
    int p   = blockIdx.x * 64 + (tid & 63);
    int bb  = blockIdx.y;
    const float* xb = prompt + bb * CHW + p;
    float xr[64];
#pragma unroll
    for (int c = 0; c < 64; c++) xr[c] = xb[c * HW];
    float4* yb = (float4*)(g_q + bb * CHW + p * 64 + qtr * 16);
    const float* wbase = ws + qtr * 16 * 64;
#pragma unroll
    for (int o4 = 0; o4 < 4; o4++) {
        float a0 = bs[qtr*16 + o4*4 + 0], a1 = bs[qtr*16 + o4*4 + 1];
        float a2 = bs[qtr*16 + o4*4 + 2], a3 = bs[qtr*16 + o4*4 + 3];
#pragma unroll
        for (int c = 0; c < 64; c++) {
            float x = xr[c];
            a0 += wbase[(o4*4+0)*64 + c] * x;
            a1 += wbase[(o4*4+1)*64 + c] * x;
            a2 += wbase[(o4*4+2)*64 + c] * x;
            a3 += wbase[(o4*4+3)*64 + c] * x;
        }
        yb[o4] = make_float4(a0, a1, a2, a3);
    }
}

// ================= conv1x1 out: g_ao [p][c] -> out [c][p]
__global__ void k_convo(const float* __restrict__ wo,
                        const float* __restrict__ bo,
                        float* __restrict__ out) {
    __shared__ float ws[4096];
    __shared__ float bs[64];
    int tid = threadIdx.x;
    for (int i = tid; i < 4096; i += 256) ws[i] = wo[i];
    if (tid < 64) bs[tid] = bo[tid];
    __syncthreads();
    int qtr = tid >> 6;
    int p   = blockIdx.x * 64 + (tid & 63);
    int bb  = blockIdx.y;
    const float4* xb4 = (const float4*)(g_ao + bb * CHW + p * 64);
    float xr[64];
#pragma unroll
    for (int c4 = 0; c4 < 16; c4++) {
        float4 v = xb4[c4];
        xr[c4*4+0] = v.x; xr[c4*4+1] = v.y; xr[c4*4+2] = v.z; xr[c4*4+3] = v.w;
    }
    float* yb = out + bb * CHW + (qtr * 16) * HW + p;
    const float* wbase = ws + qtr * 16 * 64;
#pragma unroll
    for (int o4 = 0; o4 < 4; o4++) {
        float a0 = bs[qtr*16 + o4*4 + 0], a1 = bs[qtr*16 + o4*4 + 1];
        float a2 = bs[qtr*16 + o4*4 + 2], a3 = bs[qtr*16 + o4*4 + 3];
#pragma unroll
        for (int c = 0; c < 64; c++) {
            float x = xr[c];
            a0 += wbase[(o4*4+0)*64 + c] * x;
            a1 += wbase[(o4*4+1)*64 + c] * x;
            a2 += wbase[(o4*4+2)*64 + c] * x;
            a3 += wbase[(o4*4+3)*64 + c] * x;
        }
        yb[(o4*4+0) * HW] = a0;
        yb[(o4*4+1) * HW] = a1;
        yb[(o4*4+2) * HW] = a2;
        yb[(o4*4+3) * HW] = a3;
    }
}

// ================= fused: dw3x3 + LN + GELU + offset + tanh + bilinear + K/V proj
__global__ void k_fuse(const float* __restrict__ kv,
                       const float* __restrict__ dw_w,
                       const float* __restrict__ dw_b,
                       const float* __restrict__ ln_w,
                       const float* __restrict__ ln_b,
                       const float* __restrict__ off_w,
                       const float* __restrict__ wk,
                       const float* __restrict__ bk,
                       const float* __restrict__ wv,
                       const float* __restrict__ bv) {
    __shared__ float s_wk[4096], s_wv[4096];
    __shared__ float s_dw[576], s_dwb[64], s_lnw[64], s_lnb[64];
    __shared__ float s_offw[128], s_bk[64], s_bv[64];

    for (int i = threadIdx.x; i < 4096; i += 128) { s_wk[i] = wk[i]; s_wv[i] = wv[i]; }
    for (int i = threadIdx.x; i < 576; i += 128) s_dw[i] = dw_w[i];
    if (threadIdx.x < 64) {
        s_dwb[threadIdx.x] = dw_b[threadIdx.x];
        s_lnw[threadIdx.x] = ln_w[threadIdx.x];
        s_lnb[threadIdx.x] = ln_b[threadIdx.x];
        s_bk[threadIdx.x]  = bk[threadIdx.x];
        s_bv[threadIdx.x]  = bv[threadIdx.x];
    }
    if (threadIdx.x < 128) s_offw[threadIdx.x] = off_w[threadIdx.x];
    __syncthreads();

    int p  = blockIdx.x * 128 + threadIdx.x;
    int bb = blockIdx.y;
    int py = p >> 6;
    int px = p & 63;

    const float* qb = g_q + bb * CHW;   // [p][c]

    float t[64];
#pragma unroll
    for (int c = 0; c < 64; c++) t[c] = s_dwb[c];

    for (int k9 = 0; k9 < 9; k9++) {
        int dy = k9 / 3 - 1, dx = k9 % 3 - 1;
        int yy = py + dy, xx = px + dx;
        if (yy < 0 || yy > 63 || xx < 0 || xx > 63) continue;
        const float4* qp = (const float4*)(qb + (yy * 64 + xx) * 64);
#pragma unroll
        for (int c4 = 0; c4 < 16; c4++) {
            float4 qv = qp[c4];
            t[c4*4+0] += qv.x * s_dw[(c4*4+0)*9 + k9];
            t[c4*4+1] += qv.y * s_dw[(c4*4+1)*9 + k9];
            t[c4*4+2] += qv.z * s_dw[(c4*4+2)*9 + k9];
            t[c4*4+3] += qv.w * s_dw[(c4*4+3)*9 + k9];
        }
    }

    float mu = 0.f;
#pragma unroll
    for (int c = 0; c < 64; c++) mu += t[c];
    mu *= (1.0f / 64.0f);
    float var = 0.f;
#pragma unroll
    for (int c = 0; c < 64; c++) { float d = t[c] - mu; var += d * d; }
    var *= (1.0f / 64.0f);
    float rstd = rsqrtf(var + EPSV);
#pragma unroll
    for (int c = 0; c < 64; c++) {
        float z = (t[c] - mu) * rstd * s_lnw[c] + s_lnb[c];
        t[c] = 0.5f * z * (1.0f + erff(z * 0.70710678118654752f));
    }

    float o0 = 0.f, o1 = 0.f;
#pragma unroll
    for (int c = 0; c < 64; c++) { o0 += s_offw[c] * t[c]; o1 += s_offw[64 + c] * t[c]; }
    float off0 = tanhf(o0) * (1.0f / 63.0f) * OFRV;
    float off1 = tanhf(o1) * (1.0f / 63.0f) * OFRV;

    float refy = (0.5f + (float)py) * (2.0f / 63.0f) - 1.0f;
    float refx = (0.5f + (float)px) * (2.0f / 63.0f) - 1.0f;
    float gx = (off1 + refx + 1.0f) * 0.5f * 63.0f;
    float gy = (off0 + refy + 1.0f) * 0.5f * 63.0f;

    float x0f = floorf(gx), y0f = floorf(gy);
    float wx = gx - x0f, wy = gy - y0f;
    int x0 = (int)x0f, y0 = (int)y0f;
    int x1 = x0 + 1,   y1 = y0 + 1;

    float m00 = (x0 >= 0 && x0 <= 63 && y0 >= 0 && y0 <= 63) ? 1.f : 0.f;
    float m01 = (x1 >= 0 && x1 <= 63 && y0 >= 0 && y0 <= 63) ? 1.f : 0.f;
    float m10 = (x0 >= 0 && x0 <= 63 && y1 >= 0 && y1 <= 63) ? 1.f : 0.f;
    float m11 = (x1 >= 0 && x1 <= 63 && y1 >= 0 && y1 <= 63) ? 1.f : 0.f;

    int xc0 = min(max(x0, 0), 63), xc1 = min(max(x1, 0), 63);
    int yc0 = min(max(y0, 0), 63), yc1 = min(max(y1, 0), 63);

    float w00 = m00 * (1.0f - wx) * (1.0f - wy);
    float w01 = m01 * wx * (1.0f - wy);
    float w10 = m10 * (1.0f - wx) * wy;
    float w11 = m11 * wx * wy;

    int i00 = yc0 * 64 + xc0, i01 = yc0 * 64 + xc1;
    int i10 = yc1 * 64 + xc0, i11 = yc1 * 64 + xc1;

    const float* kvb = kv + bb * CHW;
#pragma unroll
    for (int c = 0; c < 64; c++) {
        const float* kc = kvb + c * HW;
        t[c] = w00 * kc[i00] + w01 * kc[i01] + w10 * kc[i10] + w11 * kc[i11];
    }

    float* kout = g_k + bb * CHW + p * 64;   // [n][c]
    float* vout = g_v + bb * CHW + p * 64;   // [n][c]
    for (int o4 = 0; o4 < 16; o4++) {
        float ka[4], va[4];
#pragma unroll
        for (int i = 0; i < 4; i++) { ka[i] = s_bk[o4*4+i]; va[i] = s_bv[o4*4+i]; }
#pragma unroll
        for (int c = 0; c < 64; c++) {
            float x = t[c];
#pragma unroll
            for (int i = 0; i < 4; i++) {
                ka[i] += s_wk[(o4*4+i)*64 + c] * x;
                va[i] += s_wv[(o4*4+i)*64 + c] * x;
            }
        }
        ((float4*)kout)[o4] = make_float4(ka[0], ka[1], ka[2], ka[3]);
        ((float4*)vout)[o4] = make_float4(va[0], va[1], va[2], va[3]);
    }
}

// ================= V column sums (exact fp32, deterministic) =================
__global__ void k_vsum() {
    __shared__ float red[512];
    int tid = threadIdx.x;
    int bb  = blockIdx.x;
    int seg = tid >> 6;
    int c   = tid & 63;
    const float* vb = g_v + bb * CHW + c;
    float acc = 0.f;
    int n0 = seg * 512;
    for (int i = 0; i < 512; i += 4) {
        acc += vb[(n0 + i    ) * 64];
        acc += vb[(n0 + i + 1) * 64];
        acc += vb[(n0 + i + 2) * 64];
        acc += vb[(n0 + i + 3) * 64];
    }
    red[seg * 64 + c] = acc;
    __syncthreads();
    if (tid < 64) {
        float s = 0.f;
#pragma unroll
        for (int g = 0; g < 8; g++) s += red[g * 64 + tid];
        g_vsum[bb * 64 + tid] = s;
    }
}

// ================= mma.sync tf32 flash attention =================
// 256 thr = 8 warps. 128 queries/CTA. Warp w: query pair-block qw=w&3 (32 q),
// key half kh=w>>2 (64 keys of each 128-key tile). Each warp carries TWO
// m16 A-operands so every K/V B-fragment load feeds 2 MMAs (LDS/MMA 2.25->1.25).
// P' = exp(s)-1 trick; rowsum = 4096 + sum P'; O = P'V + colsum(V).
#define KSTR 68
#define VSTR 72
#define PSTR 132
#define KS0 0
#define KS1 (128*KSTR)
#define VS0 (2*128*KSTR)
#define VS1 (2*128*KSTR + 128*VSTR)
#define PS  (2*128*KSTR + 2*128*VSTR)
#define ATTN_SMEM ((2*128*KSTR + 2*128*VSTR + 128*PSTR) * 4)

__global__ void __launch_bounds__(256) k_attn() {
    extern __shared__ float sm[];
    int tid  = threadIdx.x;
    int wid  = tid >> 5;
    int lane = tid & 31;
    int qw   = wid & 3;     // 32-query pair-block
    int kh   = wid >> 2;    // key half (0/1)
    int qr   = lane >> 2;   // 0..7
    int qc   = lane & 3;    // 0..3
    int bb = blockIdx.y;
    int m0 = blockIdx.x * 128;

    const float* qb = g_q + bb * CHW;
    const float* kb = g_k + bb * CHW;
    const float* vb = g_v + bb * CHW;

    uint32_t sbase = smem_u32(sm);

    // ---- Q fragments for 2 blocks (persist in registers) ----
    uint32_t aq[2][8][4];
#pragma unroll
    for (int blk = 0; blk < 2; blk++) {
        const float* qw_ = qb + (m0 + qw * 32 + blk * 16) * 64;
#pragma unroll
        for (int kc = 0; kc < 8; kc++) {
            aq[blk][kc][0] = __float_as_uint(qw_[ qr      * 64 + kc*8 + qc    ]);
            aq[blk][kc][1] = __float_as_uint(qw_[(qr + 8) * 64 + kc*8 + qc    ]);
            aq[blk][kc][2] = __float_as_uint(qw_[ qr      * 64 + kc*8 + qc + 4]);
            aq[blk][kc][3] = __float_as_uint(qw_[(qr + 8) * 64 + kc*8 + qc + 4]);
        }
    }

    float oacc[2][8][4];
#pragma unroll
    for (int blk = 0; blk < 2; blk++)
#pragma unroll
        for (int nc = 0; nc < 8; nc++)
#pragma unroll
            for (int j = 0; j < 4; j++) oacc[blk][nc][j] = 0.f;
    float rs00 = 0.f, rs01 = 0.f, rs10 = 0.f, rs11 = 0.f;

    // ---- prefetch tile 0 (128 keys), 256 threads x 8 ----
    {
#pragma unroll
        for (int it = 0; it < 8; it++) {
            int idx = tid + it * 256;          // 0..2047
            int key = idx >> 4, c4 = idx & 15;
            cp16(sbase + (KS0 + key * KSTR + c4 * 4) * 4, kb + key * 64 + c4 * 4);
            cp16(sbase + (VS0 + key * VSTR + c4 * 4) * 4, vb + key * 64 + c4 * 4);
        }
        CP_COMMIT();
    }

    // this warp's P quadrants: rows qw*32 + blk*16.., cols kh*64..
    float* Pw0 = sm + PS + (qw * 32     ) * PSTR + kh * 64;
    float* Pw1 = sm + PS + (qw * 32 + 16) * PSTR + kh * 64;

    for (int i = 0; i < 32; i++) {
        __syncthreads();
        if (i + 1 < 32) {
            const float* ks = kb + (i + 1) * 128 * 64;
            const float* vs = vb + (i + 1) * 128 * 64;
            uint32_t ko = ((i + 1) & 1) ? KS1 : KS0;
            uint32_t vo = ((i + 1) & 1) ? VS1 : VS0;
#pragma unroll
            for (int it = 0; it < 8; it++) {
                int idx = tid + it * 256;
                int key = idx >> 4, c4 = idx & 15;
                cp16(sbase + (ko + key * KSTR + c4 * 4) * 4, ks + key * 64 + c4 * 4);
                cp16(sbase + (vo + key * VSTR + c4 * 4) * 4, vs + key * 64 + c4 * 4);
            }
            CP_COMMIT();
            CP_WAIT1();
        } else {
            CP_WAIT0();
        }
        __syncthreads();

        const float* Ks = sm + ((i & 1) ? KS1 : KS0) + kh * 64 * KSTR;
        const float* Vs = sm + ((i & 1) ? VS1 : VS0) + kh * 64 * VSTR;

        // ---- S = Q K^T (both blocks share each K fragment) ----
#pragma unroll
        for (int nc = 0; nc < 8; nc++) {
            float s0[4] = {0.f, 0.f, 0.f, 0.f};
            float s1[4] = {0.f, 0.f, 0.f, 0.f};
            const float* kr0 = Ks + (nc * 8 + qr) * KSTR + qc;
#pragma unroll
            for (int kc = 0; kc < 8; kc++) {
                uint32_t b0 = __float_as_uint(kr0[kc * 8]);
                uint32_t b1 = __float_as_uint(kr0[kc * 8 + 4]);
                mma_tf32(s0, aq[0][kc], b0, b1, s0);
                mma_tf32(s1, aq[1][kc], b0, b1, s1);
            }
            float e00 = __expf(s0[0] * SCALEV) - 1.0f;
            float e01 = __expf(s0[1] * SCALEV) - 1.0f;
            float e02 = __expf(s0[2] * SCALEV) - 1.0f;
            float e03 = __expf(s0[3] * SCALEV) - 1.0f;
            rs00 += e00 + e01;
            rs01 += e02 + e03;
            *(float2*)(Pw0 +  qr      * PSTR + nc * 8 + 2 * qc) = make_float2(e00, e01);
            *(float2*)(Pw0 + (qr + 8) * PSTR + nc * 8 + 2 * qc) = make_float2(e02, e03);
            float e10 = __expf(s1[0] * SCALEV) - 1.0f;
            float e11 = __expf(s1[1] * SCALEV) - 1.0f;
            float e12 = __expf(s1[2] * SCALEV) - 1.0f;
            float e13 = __expf(s1[3] * SCALEV) - 1.0f;
            rs10 += e10 + e11;
            rs11 += e12 + e13;
            *(float2*)(Pw1 +  qr      * PSTR + nc * 8 + 2 * qc) = make_float2(e10, e11);
            *(float2*)(Pw1 + (qr + 8) * PSTR + nc * 8 + 2 * qc) = make_float2(e12, e13);
        }
        __syncwarp();

        // ---- O += P' @ V (both blocks share each V fragment) ----
#pragma unroll
        for (int kc = 0; kc < 8; kc++) {
            uint32_t ap0[4], ap1[4];
            ap0[0] = __float_as_uint(Pw0[ qr      * PSTR + kc*8 + qc    ]);
            ap0[1] = __float_as_uint(Pw0[(qr + 8) * PSTR + kc*8 + qc    ]);
            ap0[2] = __float_as_uint(Pw0[ qr      * PSTR + kc*8 + qc + 4]);
            ap0[3] = __float_as_uint(Pw0[(qr + 8) * PSTR + kc*8 + qc + 4]);
            ap1[0] = __float_as_uint(Pw1[ qr      * PSTR + kc*8 + qc    ]);
            ap1[1] = __float_as_uint(Pw1[(qr + 8) * PSTR + kc*8 + qc    ]);
            ap1[2] = __float_as_uint(Pw1[ qr      * PSTR + kc*8 + qc + 4]);
            ap1[3] = __float_as_uint(Pw1[(qr + 8) * PSTR + kc*8 + qc + 4]);
            const float* vr0 = Vs + (kc * 8 + qc) * VSTR + qr;
            const float* vr1 = Vs + (kc * 8 + qc + 4) * VSTR + qr;
#pragma unroll
            for (int nc = 0; nc < 8; nc++) {
                uint32_t b0 = __float_as_uint(vr0[nc * 8]);
                uint32_t b1 = __float_as_uint(vr1[nc * 8]);
                mma_tf32(oacc[0][nc], ap0, b0, b1, oacc[0][nc]);
                mma_tf32(oacc[1][nc], ap1, b0, b1, oacc[1][nc]);
            }
        }
    }

    // ---- combine key halves (reuse K-buffer region as scratch) ----
    // scratch per qw: 2 blocks x 32 lanes x 35 floats (32 oacc + 2 rowsums, stride 35 coprime with 32)
    __syncthreads();
    float* scr = sm + qw * 2240;
    if (kh == 1) {
#pragma unroll
        for (int blk = 0; blk < 2; blk++) {
            float* s = scr + blk * 1120 + lane * 35;
#pragma unroll
            for (int nc = 0; nc < 8; nc++) {
#pragma unroll
                for (int j = 0; j < 4; j++) s[nc * 4 + j] = oacc[blk][nc][j];
            }
        }
        scr[lane * 35 + 32]        = rs00;
        scr[lane * 35 + 33]        = rs01;
        scr[1120 + lane * 35 + 32] = rs10;
        scr[1120 + lane * 35 + 33] = rs11;
    }
    __syncthreads();
    if (kh == 0) {
#pragma unroll
        for (int blk = 0; blk < 2; blk++) {
            float* s = scr + blk * 1120 + lane * 35;
#pragma unroll
            for (int nc = 0; nc < 8; nc++) {
#pragma unroll
                for (int j = 0; j < 4; j++) oacc[blk][nc][j] += s[nc * 4 + j];
            }
        }
        rs00 += scr[lane * 35 + 32];
        rs01 += scr[lane * 35 + 33];
        rs10 += scr[1120 + lane * 35 + 32];
        rs11 += scr[1120 + lane * 35 + 33];

        rs00 += __shfl_xor_sync(0xffffffffu, rs00, 1);
        rs00 += __shfl_xor_sync(0xffffffffu, rs00, 2);
        rs01 += __shfl_xor_sync(0xffffffffu, rs01, 1);
        rs01 += __shfl_xor_sync(0xffffffffu, rs01, 2);
        rs10 += __shfl_xor_sync(0xffffffffu, rs10, 1);
        rs10 += __shfl_xor_sync(0xffffffffu, rs10, 2);
        rs11 += __shfl_xor_sync(0xffffffffu, rs11, 1);
        rs11 += __shfl_xor_sync(0xffffffffu, rs11, 2);
        float inv00 = 1.0f / (4096.0f + rs00);
        float inv01 = 1.0f / (4096.0f + rs01);
        float inv10 = 1.0f / (4096.0f + rs10);
        float inv11 = 1.0f / (4096.0f + rs11);

        const float* vsum = g_vsum + bb * 64;
#pragma unroll
        for (int blk = 0; blk < 2; blk++) {
            float i0 = blk ? inv10 : inv00;
            float i1 = blk ? inv11 : inv01;
            float* ob = g_ao + bb * CHW + (m0 + qw * 32 + blk * 16) * 64;
#pragma unroll
            for (int nc = 0; nc < 8; nc++) {
                float2 vs2 = *(const float2*)(vsum + nc * 8 + 2 * qc);
                *(float2*)(ob +  qr      * 64 + nc * 8 + 2 * qc) =
                    make_float2((oacc[blk][nc][0] + vs2.x) * i0, (oacc[blk][nc][1] + vs2.y) * i0);
                *(float2*)(ob + (qr + 8) * 64 + nc * 8 + 2 * qc) =
                    make_float2((oacc[blk][nc][2] + vs2.x) * i1, (oacc[blk][nc][3] + vs2.y) * i1);
            }
        }
    }
}

// ================= launch =================
extern "C" void kernel_launch(void* const* d_in, const int* in_sizes, int n_in,
                              void* d_out, int out_size) {
    const float* prompt = (const float*)d_in[0];
    const float* kv     = (const float*)d_in[1];
    const float* wq     = (const float*)d_in[2];
    const float* bq     = (const float*)d_in[3];
    const float* wk     = (const float*)d_in[4];
    const float* bk     = (const float*)d_in[5];
    const float* wv     = (const float*)d_in[6];
    const float* bv     = (const float*)d_in[7];
    const float* wo     = (const float*)d_in[8];
    const float* bo     = (const float*)d_in[9];
    const float* dw_w   = (const float*)d_in[10];
    const float* dw_b   = (const float*)d_in[11];
    const float* ln_w   = (const float*)d_in[12];
    const float* ln_b   = (const float*)d_in[13];
    const float* off_w  = (const float*)d_in[14];
    float* out = (float*)d_out;

    cudaFuncSetAttribute(k_attn, cudaFuncAttributeMaxDynamicSharedMemorySize, ATTN_SMEM);

    k_convq<<<dim3(64, BB), 256>>>(prompt, wq, bq);
    k_fuse <<<dim3(32, BB), 128>>>(kv, dw_w, dw_b, ln_w, ln_b, off_w, wk, bk, wv, bv);
    k_vsum <<<BB, 512>>>();
    k_attn <<<dim3(32, BB), 256, ATTN_SMEM>>>();
    k_convo<<<dim3(64, BB), 256>>>(wo, bo, out);
}